// round 10
// baseline (speedup 1.0000x reference)
#include <cuda_runtime.h>
#include <cuda_bf16.h>

// IoU_31336081391713: elementwise YOLO IoU.
// Inputs: cell_nos [N,2] i32, output [N,5,5] f32, target [N,5] f32 -> IoU [N,5] f32.
// R9: warp-autonomous cp.async double-buffered pipelines. No block barriers:
// each warp owns a private 32-box tile pipeline (cp.async groups are per-thread),
// synchronized only by __syncwarp. 4 warps/block, 6 blocks/SM -> 24 independent
// warp pipelines per SM, 96KB reads in flight.

#define YI 20.0f
#define WTILE 32            // boxes per warp-tile
#define WARPS 4
#define THREADS (WARPS * 32)
#define NA 5
#define WOUT_F (WTILE * 25) // 800 floats  (3200 B, 200 float4)
#define WTGT_F (WTILE * 5)  // 160 floats  (640 B, 40 float4)
#define WCEL_I (WTILE * 2)  // 64 ints     (256 B, 16 int4)

__device__ __forceinline__ void cpa16(void* smem, const void* gmem) {
    unsigned s = (unsigned)__cvta_generic_to_shared(smem);
    asm volatile("cp.async.cg.shared.global [%0], [%1], 16;\n" :: "r"(s), "l"(gmem));
}
#define CP_COMMIT() asm volatile("cp.async.commit_group;\n" ::: "memory")
#define CP_WAIT1()  asm volatile("cp.async.wait_group 1;\n" ::: "memory")

struct WarpBuf {
    float s_out[2][WOUT_F];
    float s_tgt[2][WTGT_F];
    int   s_cel[2][WCEL_I];
    float s_res[WTGT_F];
};  // 8832 B per warp

__device__ __forceinline__ void prefetch_wtile(
    WarpBuf& W, int st, int lane, size_t b0,
    const int* __restrict__ g_cell,
    const float* __restrict__ g_out,
    const float* __restrict__ g_tgt)
{
    const float4* go4 = reinterpret_cast<const float4*>(g_out + b0 * 25);
    #pragma unroll
    for (int i = lane; i < WOUT_F / 4; i += 32) cpa16(&W.s_out[st][i * 4], go4 + i);
    const float4* gt4 = reinterpret_cast<const float4*>(g_tgt + b0 * 5);
    #pragma unroll
    for (int i = lane; i < WTGT_F / 4; i += 32) cpa16(&W.s_tgt[st][i * 4], gt4 + i);
    const int4* gc4 = reinterpret_cast<const int4*>(g_cell + b0 * 2);
    if (lane < WCEL_I / 4) cpa16(&W.s_cel[st][lane * 4], gc4 + lane);
}

__global__ __launch_bounds__(THREADS) void iou_kernel(
    const int*   __restrict__ g_cell,
    const float* __restrict__ g_out,
    const float* __restrict__ g_tgt,
    float*       __restrict__ g_res,
    int n_boxes, int n_tiles, int n_full_tiles, int total_warps)
{
    __shared__ WarpBuf WB[WARPS];

    const int lane = threadIdx.x & 31;
    const int wid  = threadIdx.x >> 5;
    const int gw   = blockIdx.x * WARPS + wid;   // global warp id
    WarpBuf& W = WB[wid];

    // prologue: stage first warp-tile into stage 0 (full tiles only)
    if (gw < n_full_tiles) {
        prefetch_wtile(W, 0, lane, (size_t)gw * WTILE, g_cell, g_out, g_tgt);
    }
    CP_COMMIT();

    int st = 0;
    for (int it = gw; it < n_tiles; it += total_warps, st ^= 1) {
        // stage next warp-tile into the other stage (overlaps wait+compute+store)
        const int nt = it + total_warps;
        if (nt < n_full_tiles) {
            prefetch_wtile(W, st ^ 1, lane, (size_t)nt * WTILE, g_cell, g_out, g_tgt);
        }
        CP_COMMIT();
        CP_WAIT1();        // this lane's stage-`st` copies complete
        __syncwarp();      // all lanes' copies complete -> cross-lane visibility

        const size_t b0 = (size_t)it * WTILE;
        const bool fullt = (it < n_full_tiles);
        int nb = n_boxes - (int)b0; if (nb > WTILE) nb = WTILE;

        if (lane < nb) {
            float ci, cj, t1, t2, t3, t4;
            float pv[NA][4];
            if (fullt) {
                ci = (float)W.s_cel[st][lane * 2 + 0] * YI + YI * 0.5f;
                cj = (float)W.s_cel[st][lane * 2 + 1] * YI + YI * 0.5f;
                const float* t = &W.s_tgt[st][lane * 5];
                t1 = t[1]; t2 = t[2]; t3 = t[3]; t4 = t[4];
                const float* o = &W.s_out[st][lane * 25];
                #pragma unroll
                for (int a = 0; a < NA; a++) {
                    pv[a][0] = o[a * 5 + 1]; pv[a][1] = o[a * 5 + 2];
                    pv[a][2] = o[a * 5 + 3]; pv[a][3] = o[a * 5 + 4];
                }
            } else {
                // tail: load straight from gmem (rare / absent for N=4M)
                const size_t b = b0 + lane;
                ci = (float)g_cell[b * 2 + 0] * YI + YI * 0.5f;
                cj = (float)g_cell[b * 2 + 1] * YI + YI * 0.5f;
                t1 = g_tgt[b * 5 + 1]; t2 = g_tgt[b * 5 + 2];
                t3 = g_tgt[b * 5 + 3]; t4 = g_tgt[b * 5 + 4];
                #pragma unroll
                for (int a = 0; a < NA; a++) {
                    pv[a][0] = g_out[b * 25 + a * 5 + 1];
                    pv[a][1] = g_out[b * 25 + a * 5 + 2];
                    pv[a][2] = g_out[b * 25 + a * 5 + 3];
                    pv[a][3] = g_out[b * 25 + a * 5 + 4];
                }
            }

            const float hg  = t3 * YI;
            const float wg  = t4 * YI;
            const float xcg = ci + t1 * YI;
            const float ycg = cj + t2 * YI;
            const float gx1 = ycg - wg * 0.5f;
            const float gy1 = xcg - hg * 0.5f;
            const float gx2 = ycg + wg * 0.5f;
            const float gy2 = xcg + hg * 0.5f;
            const float area_g = (gx2 - gx1) * (gy2 - gy1);

            #pragma unroll
            for (int a = 0; a < NA; a++) {
                const float h  = pv[a][2] * YI;
                const float w  = pv[a][3] * YI;
                const float xc = ci + pv[a][0] * YI;
                const float yc = cj + pv[a][1] * YI;
                const float px1 = yc - w * 0.5f;
                const float py1 = xc - h * 0.5f;
                const float px2 = yc + w * 0.5f;
                const float py2 = xc + h * 0.5f;
                const float area_p = (px2 - px1) * (py2 - py1);

                const float ltx = fmaxf(px1, gx1);
                const float lty = fmaxf(py1, gy1);
                const float rbx = fminf(px2, gx2);
                const float rby = fminf(py2, gy2);
                const float wx  = fmaxf(rbx - ltx, 0.0f);
                const float wy  = fmaxf(rby - lty, 0.0f);
                const float inter = wx * wy;
                const float uni   = area_p + area_g - inter;
                W.s_res[lane * 5 + a] = inter / uni;
            }
        }
        __syncwarp();      // s_res ready; also orders stage-buffer reuse

        if (fullt) {
            float4* gr4 = reinterpret_cast<float4*>(g_res + b0 * 5);
            #pragma unroll
            for (int i = lane; i < WTGT_F / 4; i += 32)
                __stcs(gr4 + i, reinterpret_cast<const float4*>(W.s_res)[i]);
        } else if (lane < nb) {
            #pragma unroll
            for (int a = 0; a < NA; a++)
                g_res[(b0 + lane) * 5 + a] = W.s_res[lane * 5 + a];
        }
    }
}

extern "C" void kernel_launch(void* const* d_in, const int* in_sizes, int n_in,
                              void* d_out, int out_size) {
    const int*   cell = (const int*)d_in[0];
    const float* outp = (const float*)d_in[1];
    const float* tgt  = (const float*)d_in[2];
    float*       res  = (float*)d_out;

    const int n_boxes = in_sizes[0] / 2;
    const int n_tiles = (n_boxes + WTILE - 1) / WTILE;
    const int n_full_tiles = n_boxes / WTILE;

    int grid = 152 * 6;               // persistent: 6 blocks/SM (35.3KB smem each)
    if (grid * WARPS > n_tiles) grid = (n_tiles + WARPS - 1) / WARPS;
    const int total_warps = grid * WARPS;
    iou_kernel<<<grid, THREADS>>>(cell, outp, tgt, res,
                                  n_boxes, n_tiles, n_full_tiles, total_warps);
}